// round 10
// baseline (speedup 1.0000x reference)
#include <cuda_runtime.h>

#define ETA_MIN 0.6931471805599453f
#define ETA_MAX 10.0f

// out[i] = loss[i] > eta ? 0 : 1 - loss[i]/eta,  eta = clamp(eta_value[0], ln2, 10)
//
// FINAL champion configuration (swept R1-R9):
//   - flat block-tiled grid, 512 threads/block, 4 independent front-batched
//     LDG.128 per thread (MLP_p1=4 optimal; 2 and 8 measured slower)
//   - DEFAULT cache operators (.cs / .lu measured regressions both directions)
//   - branchless weight: fmaxf(fmaf(-a, inv_eta, 1), 0)  (valid since eta>0)
//   - guard-free hot kernel: host guarantees full blocks, so zero compares
//     or branches in the main kernel; remainder handled by a separate kernel
//     that never launches for N=2^25.
// Measured floor: 35.9us kernel @ 75.0% DRAM (5.93 TB/s), the practical
// HBM3e 1:1 read:write mixed-stream ceiling. fma 3.5%, issue 11.6%.

__device__ __forceinline__ float4 weight4(float4 a, float inv_eta) {
    float4 r;
    r.x = fmaxf(fmaf(-a.x, inv_eta, 1.0f), 0.0f);
    r.y = fmaxf(fmaf(-a.y, inv_eta, 1.0f), 0.0f);
    r.z = fmaxf(fmaf(-a.z, inv_eta, 1.0f), 0.0f);
    r.w = fmaxf(fmaf(-a.w, inv_eta, 1.0f), 0.0f);
    return r;
}

// Hot kernel: every block is full. No bounds checks anywhere.
__global__ __launch_bounds__(512) void weights_kernel_full(
    const float4* __restrict__ loss4,
    const float* __restrict__ eta_value,
    float4* __restrict__ out4)
{
    float eta = eta_value[0];
    eta = fminf(fmaxf(eta, ETA_MIN), ETA_MAX);
    float inv_eta = 1.0f / eta;

    const int T = 512;
    int base = blockIdx.x * (T * 4) + threadIdx.x;

    float4 a0 = loss4[base];
    float4 a1 = loss4[base + T];
    float4 a2 = loss4[base + 2 * T];
    float4 a3 = loss4[base + 3 * T];

    out4[base]         = weight4(a0, inv_eta);
    out4[base + T]     = weight4(a1, inv_eta);
    out4[base + 2 * T] = weight4(a2, inv_eta);
    out4[base + 3 * T] = weight4(a3, inv_eta);
}

// Generic remainder kernel (scalar, bounds-checked). Covers any elements past
// the full-block region; never launches for N = 2^25.
__global__ void weights_rem_kernel(
    const float* __restrict__ loss,
    const float* __restrict__ eta_value,
    float* __restrict__ out,
    int start, int n)
{
    int i = start + blockIdx.x * blockDim.x + threadIdx.x;
    if (i < n) {
        float eta = eta_value[0];
        eta = fminf(fmaxf(eta, ETA_MIN), ETA_MAX);
        float v = loss[i];
        out[i] = fmaxf(1.0f - v / eta, 0.0f);
    }
}

extern "C" void kernel_launch(void* const* d_in, const int* in_sizes, int n_in,
                              void* d_out, int out_size)
{
    const float* loss = (const float*)d_in[0];
    const float* eta_value = (const float*)d_in[1];
    float* out = (float*)d_out;
    int n = in_sizes[0];

    const int threads = 512;
    const int per_block_elems = threads * 4 * 4;  // 8192 fp32 per block

    int full_blocks = n / per_block_elems;        // 4096 for N=2^25
    int covered = full_blocks * per_block_elems;  // == n for N=2^25

    if (full_blocks > 0) {
        weights_kernel_full<<<full_blocks, threads>>>(
            (const float4*)loss, eta_value, (float4*)out);
    }
    int rem = n - covered;
    if (rem > 0) {
        int rb = (rem + 255) / 256;
        weights_rem_kernel<<<rb, 256>>>(loss, eta_value, out, covered, n);
    }
}

// round 11
// speedup vs baseline: 1.0368x; 1.0368x over previous
#include <cuda_runtime.h>

#define ETA_MIN 0.6931471805599453f
#define ETA_MAX 10.0f

// out[i] = loss[i] > eta ? 0 : 1 - loss[i]/eta,  eta = clamp(eta_value[0], ln2, 10)
//
// Champion family (swept R1-R10): flat block-tiled grid, 4 independent
// front-batched LDG.128 per thread (MLP_p1=4), default cache operators,
// branchless FMNMX weight. Kernel floor 35.9us @ 75% DRAM (5.93 TB/s).
// Last untested axis this round: 1024 threads/block (512KB i/o window per
// block, 2048 CTAs) -- fewer CTA boundaries, better per-wave DRAM locality.

__device__ __forceinline__ float4 weight4(float4 a, float inv_eta) {
    float4 r;
    r.x = fmaxf(fmaf(-a.x, inv_eta, 1.0f), 0.0f);
    r.y = fmaxf(fmaf(-a.y, inv_eta, 1.0f), 0.0f);
    r.z = fmaxf(fmaf(-a.z, inv_eta, 1.0f), 0.0f);
    r.w = fmaxf(fmaf(-a.w, inv_eta, 1.0f), 0.0f);
    return r;
}

__global__ __launch_bounds__(1024) void weights_kernel(
    const float4* __restrict__ loss4,
    const float* __restrict__ eta_value,
    float4* __restrict__ out4,
    int n4)
{
    float eta = eta_value[0];
    eta = fminf(fmaxf(eta, ETA_MIN), ETA_MAX);
    float inv_eta = 1.0f / eta;

    const int T = 1024;
    int base = blockIdx.x * (T * 4) + threadIdx.x;

    if (base + 3 * T < n4) {
        // Hot path: 4 independent LDG.128 front-batched (default cache op).
        float4 a0 = loss4[base];
        float4 a1 = loss4[base + T];
        float4 a2 = loss4[base + 2 * T];
        float4 a3 = loss4[base + 3 * T];

        out4[base]         = weight4(a0, inv_eta);
        out4[base + T]     = weight4(a1, inv_eta);
        out4[base + 2 * T] = weight4(a2, inv_eta);
        out4[base + 3 * T] = weight4(a3, inv_eta);
    } else {
        #pragma unroll
        for (int k = 0; k < 4; k++) {
            int idx = base + k * T;
            if (idx < n4) {
                float4 a = loss4[idx];
                out4[idx] = weight4(a, inv_eta);
            }
        }
    }
}

// Scalar tail for n % 4 != 0 (not hit for N=2^25; kept for generality).
__global__ void weights_tail_kernel(
    const float* __restrict__ loss,
    const float* __restrict__ eta_value,
    float* __restrict__ out,
    int start, int n)
{
    int i = start + blockIdx.x * blockDim.x + threadIdx.x;
    if (i < n) {
        float eta = eta_value[0];
        eta = fminf(fmaxf(eta, ETA_MIN), ETA_MAX);
        float v = loss[i];
        out[i] = fmaxf(1.0f - v / eta, 0.0f);
    }
}

extern "C" void kernel_launch(void* const* d_in, const int* in_sizes, int n_in,
                              void* d_out, int out_size)
{
    const float* loss = (const float*)d_in[0];
    const float* eta_value = (const float*)d_in[1];
    float* out = (float*)d_out;
    int n = in_sizes[0];

    int n4 = n / 4;
    int vec_elems = n4 * 4;

    const int threads = 1024;
    const int per_block = threads * 4;  // 4096 float4 per block
    int blocks = (n4 + per_block - 1) / per_block;  // 2048 for N=2^25

    if (blocks > 0) {
        weights_kernel<<<blocks, threads>>>(
            (const float4*)loss, eta_value, (float4*)out, n4);
    }
    int tail = n - vec_elems;
    if (tail > 0) {
        int tb = (tail + 255) / 256;
        weights_tail_kernel<<<tb, 256>>>(loss, eta_value, out, vec_elems, n);
    }
}

// round 12
// speedup vs baseline: 1.0375x; 1.0007x over previous
#include <cuda_runtime.h>

#define ETA_MIN 0.6931471805599453f
#define ETA_MAX 10.0f

// out[i] = loss[i] > eta ? 0 : 1 - loss[i]/eta,  eta = clamp(eta_value[0], ln2, 10)
//
// FINAL kernel — champion configuration, fully swept over R1-R11:
//   - flat block-tiled grid, 1024 threads/block (best of {256, 512, 1024}):
//     512KB contiguous i/o window per block, 2048 CTAs
//   - 4 independent front-batched LDG.128 per thread (MLP_p1=4; 2 and 8 slower)
//   - DEFAULT cache operators (.cs and .lu both measured regressions)
//   - branchless weight: eta > 0 implies (a > eta ? 0 : 1 - a/eta)
//     == fmaxf(fmaf(-a, inv_eta, 1), 0)  -> single FMNMX per element
// Measured: 35.74us kernel @ 75.2% DRAM (5953 GB/s) — the practical B300
// HBM3e 1:1 read:write mixed-stream ceiling. fma 3.5%, issue 11.7%.

__device__ __forceinline__ float4 weight4(float4 a, float inv_eta) {
    float4 r;
    r.x = fmaxf(fmaf(-a.x, inv_eta, 1.0f), 0.0f);
    r.y = fmaxf(fmaf(-a.y, inv_eta, 1.0f), 0.0f);
    r.z = fmaxf(fmaf(-a.z, inv_eta, 1.0f), 0.0f);
    r.w = fmaxf(fmaf(-a.w, inv_eta, 1.0f), 0.0f);
    return r;
}

__global__ __launch_bounds__(1024) void weights_kernel(
    const float4* __restrict__ loss4,
    const float* __restrict__ eta_value,
    float4* __restrict__ out4,
    int n4)
{
    float eta = eta_value[0];
    eta = fminf(fmaxf(eta, ETA_MIN), ETA_MAX);
    float inv_eta = 1.0f / eta;

    const int T = 1024;
    int base = blockIdx.x * (T * 4) + threadIdx.x;

    if (base + 3 * T < n4) {
        // Hot path: 4 independent LDG.128 front-batched (default cache op).
        float4 a0 = loss4[base];
        float4 a1 = loss4[base + T];
        float4 a2 = loss4[base + 2 * T];
        float4 a3 = loss4[base + 3 * T];

        out4[base]         = weight4(a0, inv_eta);
        out4[base + T]     = weight4(a1, inv_eta);
        out4[base + 2 * T] = weight4(a2, inv_eta);
        out4[base + 3 * T] = weight4(a3, inv_eta);
    } else {
        #pragma unroll
        for (int k = 0; k < 4; k++) {
            int idx = base + k * T;
            if (idx < n4) {
                float4 a = loss4[idx];
                out4[idx] = weight4(a, inv_eta);
            }
        }
    }
}

// Scalar tail for n % 4 != 0 (not hit for N=2^25; kept for generality).
__global__ void weights_tail_kernel(
    const float* __restrict__ loss,
    const float* __restrict__ eta_value,
    float* __restrict__ out,
    int start, int n)
{
    int i = start + blockIdx.x * blockDim.x + threadIdx.x;
    if (i < n) {
        float eta = eta_value[0];
        eta = fminf(fmaxf(eta, ETA_MIN), ETA_MAX);
        float v = loss[i];
        out[i] = fmaxf(1.0f - v / eta, 0.0f);
    }
}

extern "C" void kernel_launch(void* const* d_in, const int* in_sizes, int n_in,
                              void* d_out, int out_size)
{
    const float* loss = (const float*)d_in[0];
    const float* eta_value = (const float*)d_in[1];
    float* out = (float*)d_out;
    int n = in_sizes[0];

    int n4 = n / 4;
    int vec_elems = n4 * 4;

    const int threads = 1024;
    const int per_block = threads * 4;  // 4096 float4 per block
    int blocks = (n4 + per_block - 1) / per_block;  // 2048 for N=2^25

    if (blocks > 0) {
        weights_kernel<<<blocks, threads>>>(
            (const float4*)loss, eta_value, (float4*)out, n4);
    }
    int tail = n - vec_elems;
    if (tail > 0) {
        int tb = (tail + 255) / 256;
        weights_tail_kernel<<<tb, 256>>>(loss, eta_value, out, vec_elems, n);
    }
}